// round 15
// baseline (speedup 1.0000x reference)
#include <cuda_runtime.h>
#include <cuda_fp16.h>
#include <stdint.h>
#include <math.h>

#define B_ 8
#define S_ 4096
#define D_ 1024
#define R_ 64

// ---------------- scratch (no allocations allowed) ----------------
__device__ __align__(16) __half g_xh[B_ * S_ * D_];     // 64 MB fp16(x) row-major
__device__ __align__(16) __half g_xTh[B_ * D_ * S_];    // 64 MB fp16(x)^T [B][D][S]
__device__ __align__(16) __half g_qth[R_ * D_];         // 128 KB fp16(Q)^T [64][1024]
__device__ __align__(16) __half g_xqh[B_ * S_ * R_];    // 4 MB fp16(x@Q/32)
__device__ __align__(16) __half g_ph[(size_t)B_ * S_ * S_];  // 268 MB P~ = fp16(exp(S))
__device__ float g_part[B_ * 32 * S_];                   // per-n-tile row sums
__device__ float g_inv[B_ * S_];                         // 1 / sum

// ---------------- helpers ----------------
__device__ __forceinline__ uint32_t smem_u32(const void *p) {
    uint32_t a;
    asm("{ .reg .u64 t; cvta.to.shared.u64 t, %1; cvt.u32.u64 %0, t; }" : "=r"(a) : "l"(p));
    return a;
}
__device__ __forceinline__ void cpa16(uint32_t dst, const void *src) {
    asm volatile("cp.async.cg.shared.global [%0], [%1], 16;" :: "r"(dst), "l"(src));
}
#define CP_COMMIT() asm volatile("cp.async.commit_group;" ::: "memory")
#define CP_WAIT0()  asm volatile("cp.async.wait_group 0;" ::: "memory")

__device__ __forceinline__ void mma_f16(float *d, const uint32_t *a, const uint32_t *b) {
    asm volatile(
        "mma.sync.aligned.m16n8k16.row.col.f32.f16.f16.f32 "
        "{%0,%1,%2,%3}, {%4,%5,%6,%7}, {%8,%9}, {%0,%1,%2,%3};"
        : "+f"(d[0]), "+f"(d[1]), "+f"(d[2]), "+f"(d[3])
        : "r"(a[0]), "r"(a[1]), "r"(a[2]), "r"(a[3]), "r"(b[0]), "r"(b[1]));
}
__device__ __forceinline__ void ldsm_x4(uint32_t &r0, uint32_t &r1, uint32_t &r2,
                                        uint32_t &r3, uint32_t addr) {
    asm volatile("ldmatrix.sync.aligned.m8n8.x4.shared.b16 {%0,%1,%2,%3}, [%4];"
                 : "=r"(r0), "=r"(r1), "=r"(r2), "=r"(r3) : "r"(addr));
}

// tile loader: rows x 64 halves, row stride stride_h (halves), pad-72 dst
__device__ __forceinline__ void ld_tileh(uint32_t sb, int fo_h, const __half *src,
                                         size_t stride_h, int rows, int tid, int nthr) {
    int total = rows * 8;
    for (int idx = tid; idx < total; idx += nthr) {
        int r = idx >> 3, c8 = idx & 7;
        cpa16(sb + (uint32_t)(fo_h + r * 72 + c8 * 8) * 2u,
              src + (size_t)r * stride_h + c8 * 8);
    }
}

// ---------------- k_projT smem (half offsets) ----------------
#define JO_A0 0           // [128][72]
#define JO_A1 9216
#define JO_B0 18432       // [64][72]
#define JO_B1 23040
#define SMM_PJ (27648 * 2)   // 55,296 B

// ---------------- k_qkexp smem (half offsets; R13 winner) ----------------
#define QO_A 0            // [128][72]
#define QO_B 9216         // [128][72]
#define QO_PS 18432       // [128][136] staging
#define QO_REDB 71680     // byte offset: 4x128 floats
#define SMM_QK (71680 + 2048)   // 73,728 B

// ---------------- k_pv smem (half offsets, 128-thread CTA, 2 CTAs/SM) ----------------
#define PO_P0 0           // [128][72]
#define PO_P1 9216
#define PO_XV0 18432      // [128][72]
#define PO_XV1 27648
#define SMM_PV (36864 * 2)   // 73,728 B per CTA

// =====================================================================
// Kernel 0a: g_qth[l][d] = fp16(Q[d][l])
// =====================================================================
__global__ void __launch_bounds__(256) k_cvtq(const float *__restrict__ Q) {
    int idx = blockIdx.x * 256 + threadIdx.x;
    int d = idx >> 6, l = idx & 63;
    g_qth[l * D_ + d] = __float2half_rn(Q[idx]);
}

// =====================================================================
// Kernel 0b: g_xh = fp16(x) row-major  AND  g_xTh = fp16(x)^T
// =====================================================================
__global__ void __launch_bounds__(256) k_cvt(const float *__restrict__ x) {
    __shared__ float tile[64][65];
    const int b = blockIdx.z;
    const int s0 = blockIdx.x * 64;
    const int d0 = blockIdx.y * 64;
    const int tid = threadIdx.x;
    const float *src = x + ((size_t)b * S_ + s0) * D_ + d0;
#pragma unroll
    for (int i = 0; i < 16; i++) {
        int idx = tid + i * 256;
        int r = idx >> 6, c = idx & 63;
        tile[r][c] = src[(size_t)r * D_ + c];
    }
    __syncthreads();
#pragma unroll
    for (int i = 0; i < 8; i++) {
        int idx = tid + i * 256;
        int r = idx >> 5, c2 = idx & 31;
        *reinterpret_cast<__half2 *>(g_xh + ((size_t)b * S_ + s0 + r) * D_ + d0 + 2 * c2) =
            __floats2half2_rn(tile[r][2 * c2], tile[r][2 * c2 + 1]);
    }
#pragma unroll
    for (int i = 0; i < 8; i++) {
        int idx = tid + i * 256;
        int dr = idx >> 5, s2 = idx & 31;
        *reinterpret_cast<__half2 *>(g_xTh + ((size_t)b * D_ + d0 + dr) * S_ + s0 + 2 * s2) =
            __floats2half2_rn(tile[2 * s2][dr], tile[2 * s2 + 1][dr]);
    }
}

// =====================================================================
// Kernel 1: k_projT — tensor GEMM  g_xqh = fp16( (xh @ Qt^T) / 32 )
// =====================================================================
__global__ void __launch_bounds__(256) k_projT() {
    extern __shared__ char smc[];
    const uint32_t sb = smem_u32(smc);
    const int tid = threadIdx.x, w = tid >> 5, lane = tid & 31;
    const int g = lane >> 2, tg = lane & 3;
    const int wm = w >> 2, wn = w & 3;
    const int m0 = wm * 64, n0s = wn * 16;
    const int row0 = blockIdx.x * 128;

    const int a_row = lane & 15, a_col = (lane >> 4) << 3;
    const int b_row = (lane & 7) + ((lane >> 4) << 3), b_col = lane & 8;

    const __half *xh = g_xh + (size_t)row0 * D_;

    ld_tileh(sb, JO_A0, xh, D_, 128, tid, 256);
    ld_tileh(sb, JO_B0, g_qth, D_, 64, tid, 256);
    CP_COMMIT();

    float sacc[4][2][4];
#pragma unroll
    for (int mi = 0; mi < 4; mi++)
#pragma unroll
        for (int ni = 0; ni < 2; ni++)
#pragma unroll
            for (int c = 0; c < 4; c++) sacc[mi][ni][c] = 0.f;

    for (int kb = 0; kb < 16; kb++) {
        CP_WAIT0();
        __syncthreads();
        if (kb + 1 < 16) {
            int nb = (kb + 1) & 1;
            ld_tileh(sb, nb ? JO_A1 : JO_A0, xh + (size_t)(kb + 1) * 64, D_, 128, tid, 256);
            ld_tileh(sb, nb ? JO_B1 : JO_B0, g_qth + (size_t)(kb + 1) * 64, D_, 64, tid, 256);
            CP_COMMIT();
        }
        const uint32_t ab = sb + 2u * ((kb & 1) ? JO_A1 : JO_A0);
        const uint32_t bb = sb + 2u * ((kb & 1) ? JO_B1 : JO_B0);
#pragma unroll
        for (int kk = 0; kk < 4; kk++) {
            const int c = kk * 16;
            uint32_t a[4][4], bf[2][2];
#pragma unroll
            for (int mi = 0; mi < 4; mi++)
                ldsm_x4(a[mi][0], a[mi][1], a[mi][2], a[mi][3],
                        ab + 2u * ((m0 + mi * 16 + a_row) * 72 + c + a_col));
            {
                uint32_t r0, r1, r2, r3;
                ldsm_x4(r0, r1, r2, r3, bb + 2u * ((n0s + b_row) * 72 + c + b_col));
                bf[0][0] = r0; bf[0][1] = r1;
                bf[1][0] = r2; bf[1][1] = r3;
            }
#pragma unroll
            for (int mi = 0; mi < 4; mi++)
#pragma unroll
                for (int ni = 0; ni < 2; ni++) mma_f16(sacc[mi][ni], a[mi], bf[ni]);
        }
        __syncthreads();
    }

    const float scale = 0.03125f;
#pragma unroll
    for (int mi = 0; mi < 4; mi++) {
        int r0 = row0 + m0 + mi * 16 + g;
#pragma unroll
        for (int ni = 0; ni < 2; ni++) {
            int cc = n0s + ni * 8 + 2 * tg;
            *reinterpret_cast<__half2 *>(g_xqh + (size_t)r0 * R_ + cc) =
                __floats2half2_rn(sacc[mi][ni][0] * scale, sacc[mi][ni][1] * scale);
            *reinterpret_cast<__half2 *>(g_xqh + (size_t)(r0 + 8) * R_ + cc) =
                __floats2half2_rn(sacc[mi][ni][2] * scale, sacc[mi][ni][3] * scale);
        }
    }
}

// =====================================================================
// Kernel 2: k_qkexp — per (128q x 128n) tile of ONE batch (arg b).
// R13 winner body; grid (32 ngrp, 32 qgrp).
// =====================================================================
__global__ void __launch_bounds__(256) k_qkexp(int b) {
    extern __shared__ char smc[];
    __half *smh = reinterpret_cast<__half *>(smc);
    const uint32_t sb = smem_u32(smc);
    const int tid = threadIdx.x, w = tid >> 5, lane = tid & 31;
    const int g = lane >> 2, tg = lane & 3;
    const int wm = w >> 2, wn = w & 3;
    const int m0 = wm * 64, n0 = wn * 32;
    const int q0 = blockIdx.y * 128, ng = blockIdx.x * 128;

    const int a_row = lane & 15, a_col = (lane >> 4) << 3;
    const int b_row = (lane & 7) + ((lane >> 4) << 3), b_col = lane & 8;

    ld_tileh(sb, QO_A, g_xqh + ((size_t)b * S_ + q0) * R_, R_, 128, tid, 256);
    ld_tileh(sb, QO_B, g_xqh + ((size_t)b * S_ + ng) * R_, R_, 128, tid, 256);
    CP_COMMIT();
    CP_WAIT0();
    __syncthreads();

    float sacc[4][4][4];
#pragma unroll
    for (int mi = 0; mi < 4; mi++)
#pragma unroll
        for (int nj = 0; nj < 4; nj++)
#pragma unroll
            for (int c = 0; c < 4; c++) sacc[mi][nj][c] = 0.f;

#pragma unroll
    for (int kk = 0; kk < 4; kk++) {
        const int c = kk * 16;
        uint32_t a[4][4], bf[4][2];
#pragma unroll
        for (int mi = 0; mi < 4; mi++)
            ldsm_x4(a[mi][0], a[mi][1], a[mi][2], a[mi][3],
                    sb + 2u * (QO_A + (m0 + mi * 16 + a_row) * 72 + c + a_col));
#pragma unroll
        for (int np = 0; np < 2; np++) {
            uint32_t r0, r1, r2, r3;
            ldsm_x4(r0, r1, r2, r3,
                    sb + 2u * (QO_B + (n0 + np * 16 + b_row) * 72 + c + b_col));
            bf[2 * np][0] = r0; bf[2 * np][1] = r1;
            bf[2 * np + 1][0] = r2; bf[2 * np + 1][1] = r3;
        }
#pragma unroll
        for (int mi = 0; mi < 4; mi++)
#pragma unroll
            for (int nj = 0; nj < 4; nj++) mma_f16(sacc[mi][nj], a[mi], bf[nj]);
    }

    float s0[4], s1[4];
#pragma unroll
    for (int mi = 0; mi < 4; mi++) { s0[mi] = 0.f; s1[mi] = 0.f; }
#pragma unroll
    for (int mi = 0; mi < 4; mi++) {
        int r0 = m0 + mi * 16 + g;
#pragma unroll
        for (int nj = 0; nj < 4; nj++) {
            float e0 = __expf(sacc[mi][nj][0]);
            float e1 = __expf(sacc[mi][nj][1]);
            float e2 = __expf(sacc[mi][nj][2]);
            float e3 = __expf(sacc[mi][nj][3]);
            s0[mi] += e0 + e1;
            s1[mi] += e2 + e3;
            int col = n0 + nj * 8 + 2 * tg;
            *reinterpret_cast<__half2 *>(smh + QO_PS + r0 * 136 + col) =
                __floats2half2_rn(e0, e1);
            *reinterpret_cast<__half2 *>(smh + QO_PS + (r0 + 8) * 136 + col) =
                __floats2half2_rn(e2, e3);
        }
    }
#pragma unroll
    for (int off = 1; off <= 2; off <<= 1)
#pragma unroll
        for (int mi = 0; mi < 4; mi++) {
            s0[mi] += __shfl_xor_sync(0xffffffffu, s0[mi], off);
            s1[mi] += __shfl_xor_sync(0xffffffffu, s1[mi], off);
        }
    float *red = reinterpret_cast<float *>(smc + QO_REDB);
    if (tg == 0) {
#pragma unroll
        for (int mi = 0; mi < 4; mi++) {
            red[wn * 128 + m0 + mi * 16 + g] = s0[mi];
            red[wn * 128 + m0 + mi * 16 + 8 + g] = s1[mi];
        }
    }
    __syncthreads();

    __half *pdst = g_ph + ((size_t)b * S_ + q0) * S_ + ng;
#pragma unroll
    for (int i = 0; i < 8; i++) {
        int idx = tid + i * 256;
        int row = idx >> 4, seg = idx & 15;
        uint4 v = *reinterpret_cast<const uint4 *>(smh + QO_PS + row * 136 + seg * 8);
        *reinterpret_cast<uint4 *>(pdst + (size_t)row * S_ + seg * 8) = v;
    }
    if (tid < 128) {
        float s = red[tid] + red[128 + tid] + red[256 + tid] + red[384 + tid];
        g_part[((size_t)b * 32 + blockIdx.x) * S_ + q0 + tid] = s;
    }
}

// =====================================================================
// Kernel 3: k_red — g_inv (batch b) = 1 / sum over 32 n-tile partials
// =====================================================================
__global__ void __launch_bounds__(256) k_red(int b) {
    int row = blockIdx.x * 256 + threadIdx.x;   // 0..S-1
    float s = 0.f;
#pragma unroll 8
    for (int nt = 0; nt < 32; nt++) s += g_part[((size_t)b * 32 + nt) * S_ + row];
    g_inv[b * S_ + row] = 1.0f / s;
}

// =====================================================================
// Kernel 4: k_pv — pure GEMM for ONE batch (arg b). R11 winner body.
// 128 threads/CTA (4 warps, 2m x 2n, warp tile 64x64), 2 CTAs/SM.
// =====================================================================
__global__ void __launch_bounds__(128, 2) k_pv(int b, float *__restrict__ out) {
    extern __shared__ char smc[];
    const uint32_t sb = smem_u32(smc);
    const int tid = threadIdx.x, w = tid >> 5, lane = tid & 31;
    const int g = lane >> 2, tg = lane & 3;
    const int wm = w >> 1, wn = w & 1;
    const int m0 = wm * 64, n0 = wn * 64;
    const int q0 = blockIdx.x * 128, d0 = blockIdx.y * 128;

    const int a_row = lane & 15, a_col = (lane >> 4) << 3;
    const int b_row = (lane & 7) + ((lane >> 4) << 3), b_col = lane & 8;

    const __half *ph = g_ph + ((size_t)b * S_ + q0) * S_;
    const __half *xvt = g_xTh + ((size_t)b * D_ + d0) * S_;

    ld_tileh(sb, PO_P0, ph, S_, 128, tid, 128);
    ld_tileh(sb, PO_XV0, xvt, S_, 128, tid, 128);
    CP_COMMIT();
    CP_WAIT0();
    __syncthreads();

    float ri[4][2];
#pragma unroll
    for (int mi = 0; mi < 4; mi++) {
        ri[mi][0] = g_inv[(size_t)b * S_ + q0 + m0 + mi * 16 + g];
        ri[mi][1] = g_inv[(size_t)b * S_ + q0 + m0 + mi * 16 + 8 + g];
    }

    float yacc[4][8][4];
#pragma unroll
    for (int mi = 0; mi < 4; mi++)
#pragma unroll
        for (int nj = 0; nj < 8; nj++)
#pragma unroll
            for (int c = 0; c < 4; c++) yacc[mi][nj][c] = 0.f;

    for (int kb = 0; kb < 64; kb++) {
        if (kb + 1 < 64) {
            int nb = (kb + 1) & 1;
            ld_tileh(sb, nb ? PO_P1 : PO_P0, ph + (size_t)(kb + 1) * 64, S_, 128, tid, 128);
            ld_tileh(sb, nb ? PO_XV1 : PO_XV0, xvt + (size_t)(kb + 1) * 64, S_, 128, tid, 128);
            CP_COMMIT();
        }
        const uint32_t psb = sb + 2u * ((kb & 1) ? PO_P1 : PO_P0);
        const uint32_t xvb = sb + 2u * ((kb & 1) ? PO_XV1 : PO_XV0);
#pragma unroll
        for (int kk = 0; kk < 4; kk++) {
            const int c = kk * 16;
            uint32_t a[4][4], bf[8][2];
#pragma unroll
            for (int mi = 0; mi < 4; mi++)
                ldsm_x4(a[mi][0], a[mi][1], a[mi][2], a[mi][3],
                        psb + 2u * ((m0 + mi * 16 + a_row) * 72 + c + a_col));
#pragma unroll
            for (int np = 0; np < 4; np++) {
                uint32_t r0, r1, r2, r3;
                ldsm_x4(r0, r1, r2, r3,
                        xvb + 2u * ((n0 + np * 16 + b_row) * 72 + c + b_col));
                bf[2 * np][0] = r0; bf[2 * np][1] = r1;
                bf[2 * np + 1][0] = r2; bf[2 * np + 1][1] = r3;
            }
#pragma unroll
            for (int mi = 0; mi < 4; mi++)
#pragma unroll
                for (int nj = 0; nj < 8; nj++) mma_f16(yacc[mi][nj], a[mi], bf[nj]);
        }
        if (kb + 1 < 64) {
            CP_WAIT0();
            __syncthreads();
        }
    }

#pragma unroll
    for (int mi = 0; mi < 4; mi++) {
        size_t rbase = ((size_t)b * S_ + q0 + m0 + mi * 16 + g) * D_ + d0 + n0 + 2 * tg;
#pragma unroll
        for (int nj = 0; nj < 8; nj++) {
            *reinterpret_cast<float2 *>(out + rbase + nj * 8) =
                make_float2(yacc[mi][nj][0] * ri[mi][0], yacc[mi][nj][1] * ri[mi][0]);
            *reinterpret_cast<float2 *>(out + rbase + nj * 8 + (size_t)8 * D_) =
                make_float2(yacc[mi][nj][2] * ri[mi][1], yacc[mi][nj][3] * ri[mi][1]);
        }
    }
}

// =====================================================================
extern "C" void kernel_launch(void *const *d_in, const int *in_sizes, int n_in,
                              void *d_out, int out_size) {
    const float *x = (const float *)d_in[0];
    const float *Q = (const float *)d_in[1];
    float *out = (float *)d_out;

    // Streams/events created once on the FIRST call (the correctness run,
    // which is NOT graph-captured). Capture calls only record/wait — legal.
    static cudaStream_t s1 = nullptr, s2 = nullptr;
    static cudaEvent_t evRoot = nullptr, evDone = nullptr, evQK[B_];
    if (!s1) {
        cudaStreamCreateWithFlags(&s1, cudaStreamNonBlocking);
        cudaStreamCreateWithFlags(&s2, cudaStreamNonBlocking);
        cudaEventCreateWithFlags(&evRoot, cudaEventDisableTiming);
        cudaEventCreateWithFlags(&evDone, cudaEventDisableTiming);
        for (int b = 0; b < B_; b++)
            cudaEventCreateWithFlags(&evQK[b], cudaEventDisableTiming);
        cudaFuncSetAttribute(k_projT, cudaFuncAttributeMaxDynamicSharedMemorySize, SMM_PJ);
        cudaFuncSetAttribute(k_qkexp, cudaFuncAttributeMaxDynamicSharedMemorySize, SMM_QK);
        cudaFuncSetAttribute(k_pv, cudaFuncAttributeMaxDynamicSharedMemorySize, SMM_PV);
    }

    // fork from the launch (capture-origin) stream
    cudaEventRecord(evRoot, 0);
    cudaStreamWaitEvent(s1, evRoot, 0);

    k_cvtq<<<(D_ * R_) / 256, 256, 0, s1>>>(Q);
    k_cvt<<<dim3(S_ / 64, D_ / 64, B_), 256, 0, s1>>>(x);
    k_projT<<<(B_ * S_) / 128, 256, SMM_PJ, s1>>>();

    for (int b = 0; b < B_; b++) {
        k_qkexp<<<dim3(S_ / 128, S_ / 128), 256, SMM_QK, s1>>>(b);
        cudaEventRecord(evQK[b], s1);
    }
    for (int b = 0; b < B_; b++) {
        cudaStreamWaitEvent(s2, evQK[b], 0);
        k_red<<<S_ / 256, 256, 0, s2>>>(b);
        k_pv<<<dim3(S_ / 128, D_ / 128), 128, SMM_PV, s2>>>(b, out);
    }

    // join back to the origin stream (all s1 work is an ancestor of pv(7))
    cudaEventRecord(evDone, s2);
    cudaStreamWaitEvent(0, evDone, 0);
}

// round 16
// speedup vs baseline: 1.1107x; 1.1107x over previous
#include <cuda_runtime.h>
#include <cuda_fp16.h>
#include <stdint.h>
#include <math.h>

#define B_ 8
#define S_ 4096
#define D_ 1024
#define R_ 64

// ---------------- scratch (no allocations allowed) ----------------
__device__ __align__(16) __half g_xh[B_ * S_ * D_];     // 64 MB fp16(x) row-major
__device__ __align__(16) __half g_xTh[B_ * D_ * S_];    // 64 MB fp16(x)^T [B][D][S]
__device__ __align__(16) __half g_qth[R_ * D_];         // 128 KB fp16(Q)^T [64][1024]
__device__ __align__(16) __half g_xqh[B_ * S_ * R_];    // 4 MB fp16(x@Q/32)
__device__ __align__(16) __half g_ph[(size_t)B_ * S_ * S_];  // 268 MB P~ = fp16(exp(S))
__device__ float g_part[B_ * 32 * S_];                   // per-n-tile row sums
__device__ float g_inv[B_ * S_];                         // 1 / sum

// ---------------- helpers ----------------
__device__ __forceinline__ uint32_t smem_u32(const void *p) {
    uint32_t a;
    asm("{ .reg .u64 t; cvta.to.shared.u64 t, %1; cvt.u32.u64 %0, t; }" : "=r"(a) : "l"(p));
    return a;
}
__device__ __forceinline__ void cpa16(uint32_t dst, const void *src) {
    asm volatile("cp.async.cg.shared.global [%0], [%1], 16;" :: "r"(dst), "l"(src));
}
#define CP_COMMIT() asm volatile("cp.async.commit_group;" ::: "memory")
#define CP_WAIT0()  asm volatile("cp.async.wait_group 0;" ::: "memory")

__device__ __forceinline__ void mma_f16(float *d, const uint32_t *a, const uint32_t *b) {
    asm volatile(
        "mma.sync.aligned.m16n8k16.row.col.f32.f16.f16.f32 "
        "{%0,%1,%2,%3}, {%4,%5,%6,%7}, {%8,%9}, {%0,%1,%2,%3};"
        : "+f"(d[0]), "+f"(d[1]), "+f"(d[2]), "+f"(d[3])
        : "r"(a[0]), "r"(a[1]), "r"(a[2]), "r"(a[3]), "r"(b[0]), "r"(b[1]));
}
__device__ __forceinline__ void ldsm_x4(uint32_t &r0, uint32_t &r1, uint32_t &r2,
                                        uint32_t &r3, uint32_t addr) {
    asm volatile("ldmatrix.sync.aligned.m8n8.x4.shared.b16 {%0,%1,%2,%3}, [%4];"
                 : "=r"(r0), "=r"(r1), "=r"(r2), "=r"(r3) : "r"(addr));
}

// tile loader: rows x 64 halves, row stride stride_h (halves), pad-72 dst
__device__ __forceinline__ void ld_tileh(uint32_t sb, int fo_h, const __half *src,
                                         size_t stride_h, int rows, int tid, int nthr) {
    int total = rows * 8;
    for (int idx = tid; idx < total; idx += nthr) {
        int r = idx >> 3, c8 = idx & 7;
        cpa16(sb + (uint32_t)(fo_h + r * 72 + c8 * 8) * 2u,
              src + (size_t)r * stride_h + c8 * 8);
    }
}

// ---------------- k_projT smem (half offsets) ----------------
#define JO_A0 0           // [128][72]
#define JO_A1 9216
#define JO_B0 18432       // [64][72]
#define JO_B1 23040
#define SMM_PJ (27648 * 2)   // 55,296 B

// ---------------- k_qkexp smem (half offsets; R13 winner) ----------------
#define QO_A 0            // [128][72]
#define QO_B 9216         // [128][72]
#define QO_PS 18432       // [128][136] staging
#define QO_REDB 71680     // byte offset: 4x128 floats
#define SMM_QK (71680 + 2048)   // 73,728 B

// ---------------- k_pv smem (half offsets, 128-thread CTA, 2 CTAs/SM) ----------------
#define PO_P0 0           // [128][72]
#define PO_P1 9216
#define PO_XV0 18432      // [128][72]
#define PO_XV1 27648
#define SMM_PV (36864 * 2)   // 73,728 B per CTA

// =====================================================================
// Kernel 0a: g_qth[l][d] = fp16(Q[d][l])
// =====================================================================
__global__ void __launch_bounds__(256) k_cvtq(const float *__restrict__ Q) {
    int idx = blockIdx.x * 256 + threadIdx.x;
    int d = idx >> 6, l = idx & 63;
    g_qth[l * D_ + d] = __float2half_rn(Q[idx]);
}

// =====================================================================
// Kernel 0b: g_xh = fp16(x) row-major  AND  g_xTh = fp16(x)^T
// =====================================================================
__global__ void __launch_bounds__(256) k_cvt(const float *__restrict__ x) {
    __shared__ float tile[64][65];
    const int b = blockIdx.z;
    const int s0 = blockIdx.x * 64;
    const int d0 = blockIdx.y * 64;
    const int tid = threadIdx.x;
    const float *src = x + ((size_t)b * S_ + s0) * D_ + d0;
#pragma unroll
    for (int i = 0; i < 16; i++) {
        int idx = tid + i * 256;
        int r = idx >> 6, c = idx & 63;
        tile[r][c] = src[(size_t)r * D_ + c];
    }
    __syncthreads();
#pragma unroll
    for (int i = 0; i < 8; i++) {
        int idx = tid + i * 256;
        int r = idx >> 5, c2 = idx & 31;
        *reinterpret_cast<__half2 *>(g_xh + ((size_t)b * S_ + s0 + r) * D_ + d0 + 2 * c2) =
            __floats2half2_rn(tile[r][2 * c2], tile[r][2 * c2 + 1]);
    }
#pragma unroll
    for (int i = 0; i < 8; i++) {
        int idx = tid + i * 256;
        int dr = idx >> 5, s2 = idx & 31;
        *reinterpret_cast<__half2 *>(g_xTh + ((size_t)b * D_ + d0 + dr) * S_ + s0 + 2 * s2) =
            __floats2half2_rn(tile[2 * s2][dr], tile[2 * s2 + 1][dr]);
    }
}

// =====================================================================
// Kernel 1: k_projT — tensor GEMM  g_xqh = fp16( (xh @ Qt^T) / 32 )
// =====================================================================
__global__ void __launch_bounds__(256) k_projT() {
    extern __shared__ char smc[];
    const uint32_t sb = smem_u32(smc);
    const int tid = threadIdx.x, w = tid >> 5, lane = tid & 31;
    const int g = lane >> 2, tg = lane & 3;
    const int wm = w >> 2, wn = w & 3;
    const int m0 = wm * 64, n0s = wn * 16;
    const int row0 = blockIdx.x * 128;

    const int a_row = lane & 15, a_col = (lane >> 4) << 3;
    const int b_row = (lane & 7) + ((lane >> 4) << 3), b_col = lane & 8;

    const __half *xh = g_xh + (size_t)row0 * D_;

    ld_tileh(sb, JO_A0, xh, D_, 128, tid, 256);
    ld_tileh(sb, JO_B0, g_qth, D_, 64, tid, 256);
    CP_COMMIT();

    float sacc[4][2][4];
#pragma unroll
    for (int mi = 0; mi < 4; mi++)
#pragma unroll
        for (int ni = 0; ni < 2; ni++)
#pragma unroll
            for (int c = 0; c < 4; c++) sacc[mi][ni][c] = 0.f;

    for (int kb = 0; kb < 16; kb++) {
        CP_WAIT0();
        __syncthreads();
        if (kb + 1 < 16) {
            int nb = (kb + 1) & 1;
            ld_tileh(sb, nb ? JO_A1 : JO_A0, xh + (size_t)(kb + 1) * 64, D_, 128, tid, 256);
            ld_tileh(sb, nb ? JO_B1 : JO_B0, g_qth + (size_t)(kb + 1) * 64, D_, 64, tid, 256);
            CP_COMMIT();
        }
        const uint32_t ab = sb + 2u * ((kb & 1) ? JO_A1 : JO_A0);
        const uint32_t bb = sb + 2u * ((kb & 1) ? JO_B1 : JO_B0);
#pragma unroll
        for (int kk = 0; kk < 4; kk++) {
            const int c = kk * 16;
            uint32_t a[4][4], bf[2][2];
#pragma unroll
            for (int mi = 0; mi < 4; mi++)
                ldsm_x4(a[mi][0], a[mi][1], a[mi][2], a[mi][3],
                        ab + 2u * ((m0 + mi * 16 + a_row) * 72 + c + a_col));
            {
                uint32_t r0, r1, r2, r3;
                ldsm_x4(r0, r1, r2, r3, bb + 2u * ((n0s + b_row) * 72 + c + b_col));
                bf[0][0] = r0; bf[0][1] = r1;
                bf[1][0] = r2; bf[1][1] = r3;
            }
#pragma unroll
            for (int mi = 0; mi < 4; mi++)
#pragma unroll
                for (int ni = 0; ni < 2; ni++) mma_f16(sacc[mi][ni], a[mi], bf[ni]);
        }
        __syncthreads();
    }

    const float scale = 0.03125f;
#pragma unroll
    for (int mi = 0; mi < 4; mi++) {
        int r0 = row0 + m0 + mi * 16 + g;
#pragma unroll
        for (int ni = 0; ni < 2; ni++) {
            int cc = n0s + ni * 8 + 2 * tg;
            *reinterpret_cast<__half2 *>(g_xqh + (size_t)r0 * R_ + cc) =
                __floats2half2_rn(sacc[mi][ni][0] * scale, sacc[mi][ni][1] * scale);
            *reinterpret_cast<__half2 *>(g_xqh + (size_t)(r0 + 8) * R_ + cc) =
                __floats2half2_rn(sacc[mi][ni][2] * scale, sacc[mi][ni][3] * scale);
        }
    }
}

// =====================================================================
// Kernel 2: k_qkexp — per (128q x 128n) tile; batch = blockIdx.z + zoff.
// R13 winner body; launched with grid (32, 32, 4) twice.
// =====================================================================
__global__ void __launch_bounds__(256) k_qkexp(int zoff) {
    extern __shared__ char smc[];
    __half *smh = reinterpret_cast<__half *>(smc);
    const uint32_t sb = smem_u32(smc);
    const int tid = threadIdx.x, w = tid >> 5, lane = tid & 31;
    const int g = lane >> 2, tg = lane & 3;
    const int wm = w >> 2, wn = w & 3;
    const int m0 = wm * 64, n0 = wn * 32;
    const int b = blockIdx.z + zoff;
    const int q0 = blockIdx.y * 128, ng = blockIdx.x * 128;

    const int a_row = lane & 15, a_col = (lane >> 4) << 3;
    const int b_row = (lane & 7) + ((lane >> 4) << 3), b_col = lane & 8;

    ld_tileh(sb, QO_A, g_xqh + ((size_t)b * S_ + q0) * R_, R_, 128, tid, 256);
    ld_tileh(sb, QO_B, g_xqh + ((size_t)b * S_ + ng) * R_, R_, 128, tid, 256);
    CP_COMMIT();
    CP_WAIT0();
    __syncthreads();

    float sacc[4][4][4];
#pragma unroll
    for (int mi = 0; mi < 4; mi++)
#pragma unroll
        for (int nj = 0; nj < 4; nj++)
#pragma unroll
            for (int c = 0; c < 4; c++) sacc[mi][nj][c] = 0.f;

#pragma unroll
    for (int kk = 0; kk < 4; kk++) {
        const int c = kk * 16;
        uint32_t a[4][4], bf[4][2];
#pragma unroll
        for (int mi = 0; mi < 4; mi++)
            ldsm_x4(a[mi][0], a[mi][1], a[mi][2], a[mi][3],
                    sb + 2u * (QO_A + (m0 + mi * 16 + a_row) * 72 + c + a_col));
#pragma unroll
        for (int np = 0; np < 2; np++) {
            uint32_t r0, r1, r2, r3;
            ldsm_x4(r0, r1, r2, r3,
                    sb + 2u * (QO_B + (n0 + np * 16 + b_row) * 72 + c + b_col));
            bf[2 * np][0] = r0; bf[2 * np][1] = r1;
            bf[2 * np + 1][0] = r2; bf[2 * np + 1][1] = r3;
        }
#pragma unroll
        for (int mi = 0; mi < 4; mi++)
#pragma unroll
            for (int nj = 0; nj < 4; nj++) mma_f16(sacc[mi][nj], a[mi], bf[nj]);
    }

    float s0[4], s1[4];
#pragma unroll
    for (int mi = 0; mi < 4; mi++) { s0[mi] = 0.f; s1[mi] = 0.f; }
#pragma unroll
    for (int mi = 0; mi < 4; mi++) {
        int r0 = m0 + mi * 16 + g;
#pragma unroll
        for (int nj = 0; nj < 4; nj++) {
            float e0 = __expf(sacc[mi][nj][0]);
            float e1 = __expf(sacc[mi][nj][1]);
            float e2 = __expf(sacc[mi][nj][2]);
            float e3 = __expf(sacc[mi][nj][3]);
            s0[mi] += e0 + e1;
            s1[mi] += e2 + e3;
            int col = n0 + nj * 8 + 2 * tg;
            *reinterpret_cast<__half2 *>(smh + QO_PS + r0 * 136 + col) =
                __floats2half2_rn(e0, e1);
            *reinterpret_cast<__half2 *>(smh + QO_PS + (r0 + 8) * 136 + col) =
                __floats2half2_rn(e2, e3);
        }
    }
#pragma unroll
    for (int off = 1; off <= 2; off <<= 1)
#pragma unroll
        for (int mi = 0; mi < 4; mi++) {
            s0[mi] += __shfl_xor_sync(0xffffffffu, s0[mi], off);
            s1[mi] += __shfl_xor_sync(0xffffffffu, s1[mi], off);
        }
    float *red = reinterpret_cast<float *>(smc + QO_REDB);
    if (tg == 0) {
#pragma unroll
        for (int mi = 0; mi < 4; mi++) {
            red[wn * 128 + m0 + mi * 16 + g] = s0[mi];
            red[wn * 128 + m0 + mi * 16 + 8 + g] = s1[mi];
        }
    }
    __syncthreads();

    __half *pdst = g_ph + ((size_t)b * S_ + q0) * S_ + ng;
#pragma unroll
    for (int i = 0; i < 8; i++) {
        int idx = tid + i * 256;
        int row = idx >> 4, seg = idx & 15;
        uint4 v = *reinterpret_cast<const uint4 *>(smh + QO_PS + row * 136 + seg * 8);
        *reinterpret_cast<uint4 *>(pdst + (size_t)row * S_ + seg * 8) = v;
    }
    if (tid < 128) {
        float s = red[tid] + red[128 + tid] + red[256 + tid] + red[384 + tid];
        g_part[((size_t)b * 32 + blockIdx.x) * S_ + q0 + tid] = s;
    }
}

// =====================================================================
// Kernel 3: k_red — g_inv for 4 batches starting at zoff
// =====================================================================
__global__ void __launch_bounds__(256) k_red(int zoff) {
    int idx = blockIdx.x * 256 + threadIdx.x;   // 0 .. 4*S-1
    int b = zoff + (idx >> 12), row = idx & (S_ - 1);
    float s = 0.f;
#pragma unroll 8
    for (int nt = 0; nt < 32; nt++) s += g_part[((size_t)b * 32 + nt) * S_ + row];
    g_inv[b * S_ + row] = 1.0f / s;
}

// =====================================================================
// Kernel 4: k_pv — pure GEMM; batch = blockIdx.z + zoff. R11 winner body.
// 128 threads/CTA (4 warps, 2m x 2n, warp tile 64x64), 2 CTAs/SM.
// =====================================================================
__global__ void __launch_bounds__(128, 2) k_pv(int zoff, float *__restrict__ out) {
    extern __shared__ char smc[];
    const uint32_t sb = smem_u32(smc);
    const int tid = threadIdx.x, w = tid >> 5, lane = tid & 31;
    const int g = lane >> 2, tg = lane & 3;
    const int wm = w >> 1, wn = w & 1;
    const int m0 = wm * 64, n0 = wn * 64;
    const int b = blockIdx.z + zoff;
    const int q0 = blockIdx.x * 128, d0 = blockIdx.y * 128;

    const int a_row = lane & 15, a_col = (lane >> 4) << 3;
    const int b_row = (lane & 7) + ((lane >> 4) << 3), b_col = lane & 8;

    const __half *ph = g_ph + ((size_t)b * S_ + q0) * S_;
    const __half *xvt = g_xTh + ((size_t)b * D_ + d0) * S_;

    ld_tileh(sb, PO_P0, ph, S_, 128, tid, 128);
    ld_tileh(sb, PO_XV0, xvt, S_, 128, tid, 128);
    CP_COMMIT();
    CP_WAIT0();
    __syncthreads();

    float ri[4][2];
#pragma unroll
    for (int mi = 0; mi < 4; mi++) {
        ri[mi][0] = g_inv[(size_t)b * S_ + q0 + m0 + mi * 16 + g];
        ri[mi][1] = g_inv[(size_t)b * S_ + q0 + m0 + mi * 16 + 8 + g];
    }

    float yacc[4][8][4];
#pragma unroll
    for (int mi = 0; mi < 4; mi++)
#pragma unroll
        for (int nj = 0; nj < 8; nj++)
#pragma unroll
            for (int c = 0; c < 4; c++) yacc[mi][nj][c] = 0.f;

    for (int kb = 0; kb < 64; kb++) {
        if (kb + 1 < 64) {
            int nb = (kb + 1) & 1;
            ld_tileh(sb, nb ? PO_P1 : PO_P0, ph + (size_t)(kb + 1) * 64, S_, 128, tid, 128);
            ld_tileh(sb, nb ? PO_XV1 : PO_XV0, xvt + (size_t)(kb + 1) * 64, S_, 128, tid, 128);
            CP_COMMIT();
        }
        const uint32_t psb = sb + 2u * ((kb & 1) ? PO_P1 : PO_P0);
        const uint32_t xvb = sb + 2u * ((kb & 1) ? PO_XV1 : PO_XV0);
#pragma unroll
        for (int kk = 0; kk < 4; kk++) {
            const int c = kk * 16;
            uint32_t a[4][4], bf[8][2];
#pragma unroll
            for (int mi = 0; mi < 4; mi++)
                ldsm_x4(a[mi][0], a[mi][1], a[mi][2], a[mi][3],
                        psb + 2u * ((m0 + mi * 16 + a_row) * 72 + c + a_col));
#pragma unroll
            for (int np = 0; np < 4; np++) {
                uint32_t r0, r1, r2, r3;
                ldsm_x4(r0, r1, r2, r3,
                        xvb + 2u * ((n0 + np * 16 + b_row) * 72 + c + b_col));
                bf[2 * np][0] = r0; bf[2 * np][1] = r1;
                bf[2 * np + 1][0] = r2; bf[2 * np + 1][1] = r3;
            }
#pragma unroll
            for (int mi = 0; mi < 4; mi++)
#pragma unroll
                for (int nj = 0; nj < 8; nj++) mma_f16(yacc[mi][nj], a[mi], bf[nj]);
        }
        if (kb + 1 < 64) {
            CP_WAIT0();
            __syncthreads();
        }
    }

#pragma unroll
    for (int mi = 0; mi < 4; mi++) {
        size_t rbase = ((size_t)b * S_ + q0 + m0 + mi * 16 + g) * D_ + d0 + n0 + 2 * tg;
#pragma unroll
        for (int nj = 0; nj < 8; nj++) {
            *reinterpret_cast<float2 *>(out + rbase + nj * 8) =
                make_float2(yacc[mi][nj][0] * ri[mi][0], yacc[mi][nj][1] * ri[mi][0]);
            *reinterpret_cast<float2 *>(out + rbase + nj * 8 + (size_t)8 * D_) =
                make_float2(yacc[mi][nj][2] * ri[mi][1], yacc[mi][nj][3] * ri[mi][1]);
        }
    }
}

// =====================================================================
extern "C" void kernel_launch(void *const *d_in, const int *in_sizes, int n_in,
                              void *d_out, int out_size) {
    const float *x = (const float *)d_in[0];
    const float *Q = (const float *)d_in[1];
    float *out = (float *)d_out;

    static cudaStream_t s1 = nullptr, s2 = nullptr;
    static cudaEvent_t evRoot = nullptr, evDone = nullptr, evH0 = nullptr;
    if (!s1) {
        cudaStreamCreateWithFlags(&s1, cudaStreamNonBlocking);
        cudaStreamCreateWithFlags(&s2, cudaStreamNonBlocking);
        cudaEventCreateWithFlags(&evRoot, cudaEventDisableTiming);
        cudaEventCreateWithFlags(&evDone, cudaEventDisableTiming);
        cudaEventCreateWithFlags(&evH0, cudaEventDisableTiming);
        cudaFuncSetAttribute(k_projT, cudaFuncAttributeMaxDynamicSharedMemorySize, SMM_PJ);
        cudaFuncSetAttribute(k_qkexp, cudaFuncAttributeMaxDynamicSharedMemorySize, SMM_QK);
        cudaFuncSetAttribute(k_pv, cudaFuncAttributeMaxDynamicSharedMemorySize, SMM_PV);
    }

    cudaEventRecord(evRoot, 0);
    cudaStreamWaitEvent(s1, evRoot, 0);

    k_cvtq<<<(D_ * R_) / 256, 256, 0, s1>>>(Q);
    k_cvt<<<dim3(S_ / 64, D_ / 64, B_), 256, 0, s1>>>(x);
    k_projT<<<(B_ * S_) / 128, 256, SMM_PJ, s1>>>();

    // half 1 of qkexp (batches 0-3), then signal
    k_qkexp<<<dim3(S_ / 128, S_ / 128, 4), 256, SMM_QK, s1>>>(0);
    cudaEventRecord(evH0, s1);
    // half 2 of qkexp continues on s1 while s2 runs red+pv for half 1
    k_qkexp<<<dim3(S_ / 128, S_ / 128, 4), 256, SMM_QK, s1>>>(4);

    cudaStreamWaitEvent(s2, evH0, 0);
    k_red<<<(4 * S_) / 256, 256, 0, s2>>>(0);
    k_pv<<<dim3(S_ / 128, D_ / 128, 4), 128, SMM_PV, s2>>>(0, out);

    // half 2 of pv depends on all of qkexp (s1 order ensures batches 4-7 done)
    cudaEventRecord(evDone, s1);
    cudaStreamWaitEvent(s2, evDone, 0);
    k_red<<<(4 * S_) / 256, 256, 0, s2>>>(4);
    k_pv<<<dim3(S_ / 128, D_ / 128, 4), 128, SMM_PV, s2>>>(4, out);

    cudaEventRecord(evDone, s2);
    cudaStreamWaitEvent(0, evDone, 0);
}

// round 17
// speedup vs baseline: 1.1414x; 1.0277x over previous
#include <cuda_runtime.h>
#include <cuda_fp16.h>
#include <stdint.h>
#include <math.h>

#define B_ 8
#define S_ 4096
#define D_ 1024
#define R_ 64

// ---------------- scratch (no allocations allowed) ----------------
__device__ __align__(16) __half g_xh[B_ * S_ * D_];     // 64 MB fp16(x) row-major
__device__ __align__(16) __half g_xTh[B_ * D_ * S_];    // 64 MB fp16(x)^T [B][D][S]
__device__ __align__(16) __half g_qth[R_ * D_];         // 128 KB fp16(Q)^T [64][1024]
__device__ __align__(16) __half g_xqh[B_ * S_ * R_];    // 4 MB fp16(x@Q/32)
__device__ __align__(16) __half g_ph[(size_t)B_ * S_ * S_];  // 268 MB P~ = fp16(exp(S))
__device__ float g_part[B_ * 32 * S_];                   // per-n-tile row sums
__device__ float g_inv[B_ * S_];                         // 1 / sum

// ---------------- helpers ----------------
__device__ __forceinline__ uint32_t smem_u32(const void *p) {
    uint32_t a;
    asm("{ .reg .u64 t; cvta.to.shared.u64 t, %1; cvt.u32.u64 %0, t; }" : "=r"(a) : "l"(p));
    return a;
}
__device__ __forceinline__ void cpa16(uint32_t dst, const void *src) {
    asm volatile("cp.async.cg.shared.global [%0], [%1], 16;" :: "r"(dst), "l"(src));
}
#define CP_COMMIT() asm volatile("cp.async.commit_group;" ::: "memory")
#define CP_WAIT0()  asm volatile("cp.async.wait_group 0;" ::: "memory")

__device__ __forceinline__ void mma_f16(float *d, const uint32_t *a, const uint32_t *b) {
    asm volatile(
        "mma.sync.aligned.m16n8k16.row.col.f32.f16.f16.f32 "
        "{%0,%1,%2,%3}, {%4,%5,%6,%7}, {%8,%9}, {%0,%1,%2,%3};"
        : "+f"(d[0]), "+f"(d[1]), "+f"(d[2]), "+f"(d[3])
        : "r"(a[0]), "r"(a[1]), "r"(a[2]), "r"(a[3]), "r"(b[0]), "r"(b[1]));
}
__device__ __forceinline__ void ldsm_x4(uint32_t &r0, uint32_t &r1, uint32_t &r2,
                                        uint32_t &r3, uint32_t addr) {
    asm volatile("ldmatrix.sync.aligned.m8n8.x4.shared.b16 {%0,%1,%2,%3}, [%4];"
                 : "=r"(r0), "=r"(r1), "=r"(r2), "=r"(r3) : "r"(addr));
}

// tile loader: rows x 64 halves, row stride stride_h (halves), pad-72 dst
__device__ __forceinline__ void ld_tileh(uint32_t sb, int fo_h, const __half *src,
                                         size_t stride_h, int rows, int tid, int nthr) {
    int total = rows * 8;
    for (int idx = tid; idx < total; idx += nthr) {
        int r = idx >> 3, c8 = idx & 7;
        cpa16(sb + (uint32_t)(fo_h + r * 72 + c8 * 8) * 2u,
              src + (size_t)r * stride_h + c8 * 8);
    }
}

// ---------------- k_projT smem (half offsets) ----------------
#define JO_A0 0           // [128][72]
#define JO_A1 9216
#define JO_B0 18432       // [64][72]
#define JO_B1 23040
#define SMM_PJ (27648 * 2)   // 55,296 B

// ---------------- k_qkexp smem (half offsets; R13 winner) ----------------
#define QO_A 0            // [128][72]
#define QO_B 9216         // [128][72]
#define QO_PS 18432       // [128][136] staging
#define QO_REDB 71680     // byte offset: 4x128 floats
#define SMM_QK (71680 + 2048)   // 73,728 B

// ---------------- k_pv smem (half offsets, 128-thread CTA, 2 CTAs/SM) ----------------
#define PO_P0 0           // [128][72]
#define PO_P1 9216
#define PO_XV0 18432      // [128][72]
#define PO_XV1 27648
#define SMM_PV (36864 * 2)   // 73,728 B per CTA

// =====================================================================
// Kernel 0a: g_qth[l][d] = fp16(Q[d][l])
// =====================================================================
__global__ void __launch_bounds__(256) k_cvtq(const float *__restrict__ Q) {
    int idx = blockIdx.x * 256 + threadIdx.x;
    int d = idx >> 6, l = idx & 63;
    g_qth[l * D_ + d] = __float2half_rn(Q[idx]);
}

// =====================================================================
// Kernel 0b: g_xh = fp16(x) row-major  AND  g_xTh = fp16(x)^T
// =====================================================================
__global__ void __launch_bounds__(256) k_cvt(const float *__restrict__ x) {
    __shared__ float tile[64][65];
    const int b = blockIdx.z;
    const int s0 = blockIdx.x * 64;
    const int d0 = blockIdx.y * 64;
    const int tid = threadIdx.x;
    const float *src = x + ((size_t)b * S_ + s0) * D_ + d0;
#pragma unroll
    for (int i = 0; i < 16; i++) {
        int idx = tid + i * 256;
        int r = idx >> 6, c = idx & 63;
        tile[r][c] = src[(size_t)r * D_ + c];
    }
    __syncthreads();
#pragma unroll
    for (int i = 0; i < 8; i++) {
        int idx = tid + i * 256;
        int r = idx >> 5, c2 = idx & 31;
        *reinterpret_cast<__half2 *>(g_xh + ((size_t)b * S_ + s0 + r) * D_ + d0 + 2 * c2) =
            __floats2half2_rn(tile[r][2 * c2], tile[r][2 * c2 + 1]);
    }
#pragma unroll
    for (int i = 0; i < 8; i++) {
        int idx = tid + i * 256;
        int dr = idx >> 5, s2 = idx & 31;
        *reinterpret_cast<__half2 *>(g_xTh + ((size_t)b * D_ + d0 + dr) * S_ + s0 + 2 * s2) =
            __floats2half2_rn(tile[2 * s2][dr], tile[2 * s2 + 1][dr]);
    }
}

// =====================================================================
// Kernel 1: k_projT — tensor GEMM  g_xqh = fp16( (xh @ Qt^T) / 32 )
// =====================================================================
__global__ void __launch_bounds__(256) k_projT() {
    extern __shared__ char smc[];
    const uint32_t sb = smem_u32(smc);
    const int tid = threadIdx.x, w = tid >> 5, lane = tid & 31;
    const int g = lane >> 2, tg = lane & 3;
    const int wm = w >> 2, wn = w & 3;
    const int m0 = wm * 64, n0s = wn * 16;
    const int row0 = blockIdx.x * 128;

    const int a_row = lane & 15, a_col = (lane >> 4) << 3;
    const int b_row = (lane & 7) + ((lane >> 4) << 3), b_col = lane & 8;

    const __half *xh = g_xh + (size_t)row0 * D_;

    ld_tileh(sb, JO_A0, xh, D_, 128, tid, 256);
    ld_tileh(sb, JO_B0, g_qth, D_, 64, tid, 256);
    CP_COMMIT();

    float sacc[4][2][4];
#pragma unroll
    for (int mi = 0; mi < 4; mi++)
#pragma unroll
        for (int ni = 0; ni < 2; ni++)
#pragma unroll
            for (int c = 0; c < 4; c++) sacc[mi][ni][c] = 0.f;

    for (int kb = 0; kb < 16; kb++) {
        CP_WAIT0();
        __syncthreads();
        if (kb + 1 < 16) {
            int nb = (kb + 1) & 1;
            ld_tileh(sb, nb ? JO_A1 : JO_A0, xh + (size_t)(kb + 1) * 64, D_, 128, tid, 256);
            ld_tileh(sb, nb ? JO_B1 : JO_B0, g_qth + (size_t)(kb + 1) * 64, D_, 64, tid, 256);
            CP_COMMIT();
        }
        const uint32_t ab = sb + 2u * ((kb & 1) ? JO_A1 : JO_A0);
        const uint32_t bb = sb + 2u * ((kb & 1) ? JO_B1 : JO_B0);
#pragma unroll
        for (int kk = 0; kk < 4; kk++) {
            const int c = kk * 16;
            uint32_t a[4][4], bf[2][2];
#pragma unroll
            for (int mi = 0; mi < 4; mi++)
                ldsm_x4(a[mi][0], a[mi][1], a[mi][2], a[mi][3],
                        ab + 2u * ((m0 + mi * 16 + a_row) * 72 + c + a_col));
            {
                uint32_t r0, r1, r2, r3;
                ldsm_x4(r0, r1, r2, r3, bb + 2u * ((n0s + b_row) * 72 + c + b_col));
                bf[0][0] = r0; bf[0][1] = r1;
                bf[1][0] = r2; bf[1][1] = r3;
            }
#pragma unroll
            for (int mi = 0; mi < 4; mi++)
#pragma unroll
                for (int ni = 0; ni < 2; ni++) mma_f16(sacc[mi][ni], a[mi], bf[ni]);
        }
        __syncthreads();
    }

    const float scale = 0.03125f;
#pragma unroll
    for (int mi = 0; mi < 4; mi++) {
        int r0 = row0 + m0 + mi * 16 + g;
#pragma unroll
        for (int ni = 0; ni < 2; ni++) {
            int cc = n0s + ni * 8 + 2 * tg;
            *reinterpret_cast<__half2 *>(g_xqh + (size_t)r0 * R_ + cc) =
                __floats2half2_rn(sacc[mi][ni][0] * scale, sacc[mi][ni][1] * scale);
            *reinterpret_cast<__half2 *>(g_xqh + (size_t)(r0 + 8) * R_ + cc) =
                __floats2half2_rn(sacc[mi][ni][2] * scale, sacc[mi][ni][3] * scale);
        }
    }
}

// =====================================================================
// Kernel 2: k_qkexp — per (128q x 128n): S = XQq@XQn^T, P~=fp16(exp(S)),
// partial row sums; staged coalesced writeback. (R13 body)
// __launch_bounds__(256, 3): force <=85 regs for 3 CTAs/SM residency.
// =====================================================================
__global__ void __launch_bounds__(256, 3) k_qkexp() {
    extern __shared__ char smc[];
    __half *smh = reinterpret_cast<__half *>(smc);
    const uint32_t sb = smem_u32(smc);
    const int tid = threadIdx.x, w = tid >> 5, lane = tid & 31;
    const int g = lane >> 2, tg = lane & 3;
    const int wm = w >> 2, wn = w & 3;
    const int m0 = wm * 64, n0 = wn * 32;
    const int b = blockIdx.z, q0 = blockIdx.y * 128, ng = blockIdx.x * 128;

    const int a_row = lane & 15, a_col = (lane >> 4) << 3;
    const int b_row = (lane & 7) + ((lane >> 4) << 3), b_col = lane & 8;

    ld_tileh(sb, QO_A, g_xqh + ((size_t)b * S_ + q0) * R_, R_, 128, tid, 256);
    ld_tileh(sb, QO_B, g_xqh + ((size_t)b * S_ + ng) * R_, R_, 128, tid, 256);
    CP_COMMIT();
    CP_WAIT0();
    __syncthreads();

    float sacc[4][4][4];
#pragma unroll
    for (int mi = 0; mi < 4; mi++)
#pragma unroll
        for (int nj = 0; nj < 4; nj++)
#pragma unroll
            for (int c = 0; c < 4; c++) sacc[mi][nj][c] = 0.f;

#pragma unroll
    for (int kk = 0; kk < 4; kk++) {
        const int c = kk * 16;
        uint32_t a[4][4], bf[4][2];
#pragma unroll
        for (int mi = 0; mi < 4; mi++)
            ldsm_x4(a[mi][0], a[mi][1], a[mi][2], a[mi][3],
                    sb + 2u * (QO_A + (m0 + mi * 16 + a_row) * 72 + c + a_col));
#pragma unroll
        for (int np = 0; np < 2; np++) {
            uint32_t r0, r1, r2, r3;
            ldsm_x4(r0, r1, r2, r3,
                    sb + 2u * (QO_B + (n0 + np * 16 + b_row) * 72 + c + b_col));
            bf[2 * np][0] = r0; bf[2 * np][1] = r1;
            bf[2 * np + 1][0] = r2; bf[2 * np + 1][1] = r3;
        }
#pragma unroll
        for (int mi = 0; mi < 4; mi++)
#pragma unroll
            for (int nj = 0; nj < 4; nj++) mma_f16(sacc[mi][nj], a[mi], bf[nj]);
    }

    float s0[4], s1[4];
#pragma unroll
    for (int mi = 0; mi < 4; mi++) { s0[mi] = 0.f; s1[mi] = 0.f; }
#pragma unroll
    for (int mi = 0; mi < 4; mi++) {
        int r0 = m0 + mi * 16 + g;
#pragma unroll
        for (int nj = 0; nj < 4; nj++) {
            float e0 = __expf(sacc[mi][nj][0]);
            float e1 = __expf(sacc[mi][nj][1]);
            float e2 = __expf(sacc[mi][nj][2]);
            float e3 = __expf(sacc[mi][nj][3]);
            s0[mi] += e0 + e1;
            s1[mi] += e2 + e3;
            int col = n0 + nj * 8 + 2 * tg;
            *reinterpret_cast<__half2 *>(smh + QO_PS + r0 * 136 + col) =
                __floats2half2_rn(e0, e1);
            *reinterpret_cast<__half2 *>(smh + QO_PS + (r0 + 8) * 136 + col) =
                __floats2half2_rn(e2, e3);
        }
    }
#pragma unroll
    for (int off = 1; off <= 2; off <<= 1)
#pragma unroll
        for (int mi = 0; mi < 4; mi++) {
            s0[mi] += __shfl_xor_sync(0xffffffffu, s0[mi], off);
            s1[mi] += __shfl_xor_sync(0xffffffffu, s1[mi], off);
        }
    float *red = reinterpret_cast<float *>(smc + QO_REDB);
    if (tg == 0) {
#pragma unroll
        for (int mi = 0; mi < 4; mi++) {
            red[wn * 128 + m0 + mi * 16 + g] = s0[mi];
            red[wn * 128 + m0 + mi * 16 + 8 + g] = s1[mi];
        }
    }
    __syncthreads();

    __half *pdst = g_ph + ((size_t)b * S_ + q0) * S_ + ng;
#pragma unroll
    for (int i = 0; i < 8; i++) {
        int idx = tid + i * 256;
        int row = idx >> 4, seg = idx & 15;
        uint4 v = *reinterpret_cast<const uint4 *>(smh + QO_PS + row * 136 + seg * 8);
        *reinterpret_cast<uint4 *>(pdst + (size_t)row * S_ + seg * 8) = v;
    }
    if (tid < 128) {
        float s = red[tid] + red[128 + tid] + red[256 + tid] + red[384 + tid];
        g_part[((size_t)b * 32 + blockIdx.x) * S_ + q0 + tid] = s;
    }
}

// =====================================================================
// Kernel 3: k_red — g_inv = 1 / sum over 32 n-tile partials
// =====================================================================
__global__ void __launch_bounds__(256) k_red() {
    int idx = blockIdx.x * 256 + threadIdx.x;
    int b = idx >> 12, row = idx & (S_ - 1);
    float s = 0.f;
#pragma unroll 8
    for (int nt = 0; nt < 32; nt++) s += g_part[((size_t)b * 32 + nt) * S_ + row];
    g_inv[idx] = 1.0f / s;
}

// =====================================================================
// Kernel 4: k_pv — pure GEMM  Y[q][d] = (P~ @ X) * inv.  (R11 winner)
// 128 threads/CTA (4 warps, 2m x 2n, warp tile 64x64), 2 CTAs/SM.
// =====================================================================
__global__ void __launch_bounds__(128, 2) k_pv(float *__restrict__ out) {
    extern __shared__ char smc[];
    const uint32_t sb = smem_u32(smc);
    const int tid = threadIdx.x, w = tid >> 5, lane = tid & 31;
    const int g = lane >> 2, tg = lane & 3;
    const int wm = w >> 1, wn = w & 1;
    const int m0 = wm * 64, n0 = wn * 64;
    const int b = blockIdx.z, q0 = blockIdx.x * 128, d0 = blockIdx.y * 128;

    const int a_row = lane & 15, a_col = (lane >> 4) << 3;
    const int b_row = (lane & 7) + ((lane >> 4) << 3), b_col = lane & 8;

    const __half *ph = g_ph + ((size_t)b * S_ + q0) * S_;
    const __half *xvt = g_xTh + ((size_t)b * D_ + d0) * S_;

    ld_tileh(sb, PO_P0, ph, S_, 128, tid, 128);
    ld_tileh(sb, PO_XV0, xvt, S_, 128, tid, 128);
    CP_COMMIT();
    CP_WAIT0();
    __syncthreads();

    float ri[4][2];
#pragma unroll
    for (int mi = 0; mi < 4; mi++) {
        ri[mi][0] = g_inv[(size_t)b * S_ + q0 + m0 + mi * 16 + g];
        ri[mi][1] = g_inv[(size_t)b * S_ + q0 + m0 + mi * 16 + 8 + g];
    }

    float yacc[4][8][4];
#pragma unroll
    for (int mi = 0; mi < 4; mi++)
#pragma unroll
        for (int nj = 0; nj < 8; nj++)
#pragma unroll
            for (int c = 0; c < 4; c++) yacc[mi][nj][c] = 0.f;

    for (int kb = 0; kb < 64; kb++) {
        if (kb + 1 < 64) {
            int nb = (kb + 1) & 1;
            ld_tileh(sb, nb ? PO_P1 : PO_P0, ph + (size_t)(kb + 1) * 64, S_, 128, tid, 128);
            ld_tileh(sb, nb ? PO_XV1 : PO_XV0, xvt + (size_t)(kb + 1) * 64, S_, 128, tid, 128);
            CP_COMMIT();
        }
        const uint32_t psb = sb + 2u * ((kb & 1) ? PO_P1 : PO_P0);
        const uint32_t xvb = sb + 2u * ((kb & 1) ? PO_XV1 : PO_XV0);
#pragma unroll
        for (int kk = 0; kk < 4; kk++) {
            const int c = kk * 16;
            uint32_t a[4][4], bf[8][2];
#pragma unroll
            for (int mi = 0; mi < 4; mi++)
                ldsm_x4(a[mi][0], a[mi][1], a[mi][2], a[mi][3],
                        psb + 2u * ((m0 + mi * 16 + a_row) * 72 + c + a_col));
#pragma unroll
            for (int np = 0; np < 4; np++) {
                uint32_t r0, r1, r2, r3;
                ldsm_x4(r0, r1, r2, r3,
                        xvb + 2u * ((n0 + np * 16 + b_row) * 72 + c + b_col));
                bf[2 * np][0] = r0; bf[2 * np][1] = r1;
                bf[2 * np + 1][0] = r2; bf[2 * np + 1][1] = r3;
            }
#pragma unroll
            for (int mi = 0; mi < 4; mi++)
#pragma unroll
                for (int nj = 0; nj < 8; nj++) mma_f16(yacc[mi][nj], a[mi], bf[nj]);
        }
        if (kb + 1 < 64) {
            CP_WAIT0();
            __syncthreads();
        }
    }

    // ---- epilogue: normalize + store ----
#pragma unroll
    for (int mi = 0; mi < 4; mi++) {
        size_t rbase = ((size_t)b * S_ + q0 + m0 + mi * 16 + g) * D_ + d0 + n0 + 2 * tg;
#pragma unroll
        for (int nj = 0; nj < 8; nj++) {
            *reinterpret_cast<float2 *>(out + rbase + nj * 8) =
                make_float2(yacc[mi][nj][0] * ri[mi][0], yacc[mi][nj][1] * ri[mi][0]);
            *reinterpret_cast<float2 *>(out + rbase + nj * 8 + (size_t)8 * D_) =
                make_float2(yacc[mi][nj][2] * ri[mi][1], yacc[mi][nj][3] * ri[mi][1]);
        }
    }
}

// =====================================================================
extern "C" void kernel_launch(void *const *d_in, const int *in_sizes, int n_in,
                              void *d_out, int out_size) {
    const float *x = (const float *)d_in[0];
    const float *Q = (const float *)d_in[1];
    float *out = (float *)d_out;

    cudaFuncSetAttribute(k_projT, cudaFuncAttributeMaxDynamicSharedMemorySize, SMM_PJ);
    cudaFuncSetAttribute(k_qkexp, cudaFuncAttributeMaxDynamicSharedMemorySize, SMM_QK);
    cudaFuncSetAttribute(k_pv, cudaFuncAttributeMaxDynamicSharedMemorySize, SMM_PV);

    k_cvtq<<<(D_ * R_) / 256, 256>>>(Q);
    k_cvt<<<dim3(S_ / 64, D_ / 64, B_), 256>>>(x);
    k_projT<<<(B_ * S_) / 128, 256, SMM_PJ>>>();
    k_qkexp<<<dim3(S_ / 128, S_ / 128, B_), 256, SMM_QK>>>();
    k_red<<<(B_ * S_) / 256, 256>>>();
    k_pv<<<dim3(S_ / 128, D_ / 128, B_), 128, SMM_PV>>>(out);
}